// round 15
// baseline (speedup 1.0000x reference)
#include <cuda_runtime.h>
#include <math.h>

#define BB 8
#define TT 256
#define UU 64
#define VV 512
#define U1 (UU + 1)
#define DR 320                // diag rows per batch (t+u in 0..319)
#define BS 66                 // blank diag-row stride (col = u+1, even stride)
#define ES 64                 // emit diag-row stride (col = u)
#define NEGF (-1e30f)
#define LOG2E 1.4426950408889634f
#define LN2   0.6931471805599453f

// Diag-major scratch (log2 domain). blank(t,u) -> [b][t+u][u+1]; emit(t,u) ->
// [b][t+u][u]. Unwritten slots stay 0 from .bss (never stored to) and act as
// the guard zeros of the branch-free DP recurrence.
__device__ float g_blank_d[BB * DR * BS];
__device__ float g_emit_d [BB * DR * ES];
__device__ float g_loss   [BB];
__device__ int   g_fin;                   // finalize ticket; self-resets

__device__ __forceinline__ float ex2_fast(float x)
{
    float r; asm("ex2.approx.ftz.f32 %0, %1;" : "=f"(r) : "f"(x)); return r;
}
__device__ __forceinline__ float lg2_fast(float x)
{
    float r; asm("lg2.approx.f32 %0, %1;" : "=f"(r) : "f"(x)); return r;
}

// ---------------------------------------------------------------------------
// Kernel 1: per-row logsumexp over V=512 -> blank/emit log2-probs, written
// DIAG-MAJOR. One warp per (b,t,u) row; emit via direct gather.
// ---------------------------------------------------------------------------
__global__ void __launch_bounds__(256) rnnt_softmax_kernel(
    const float* __restrict__ pred, const int* __restrict__ target)
{
    const int warp = (blockIdx.x * blockDim.x + threadIdx.x) >> 5;
    const int lane = threadIdx.x & 31;
    const int rows = BB * TT * U1;
    if (warp >= rows) return;

    const int b   = warp / (TT * U1);
    const int rem = warp % (TT * U1);
    const int t   = rem / U1;
    const int u   = rem % U1;

    const float* rowp = pred + (size_t)warp * VV;
    const float4* row4 = reinterpret_cast<const float4*>(rowp);

    const int tgt = (u < UU) ? target[b * UU + u] : 0;
    const float ev = __ldg(rowp + tgt);

    float4 v0 = row4[lane];
    float4 v1 = row4[lane + 32];
    float4 v2 = row4[lane + 64];
    float4 v3 = row4[lane + 96];

    float m = fmaxf(fmaxf(fmaxf(v0.x, v0.y), fmaxf(v0.z, v0.w)),
                    fmaxf(fmaxf(v1.x, v1.y), fmaxf(v1.z, v1.w)));
    m = fmaxf(m, fmaxf(fmaxf(fmaxf(v2.x, v2.y), fmaxf(v2.z, v2.w)),
                       fmaxf(fmaxf(v3.x, v3.y), fmaxf(v3.z, v3.w))));
    #pragma unroll
    for (int o = 16; o > 0; o >>= 1) m = fmaxf(m, __shfl_xor_sync(0xffffffffu, m, o));

    float s = 0.f;
    s += ex2_fast((v0.x - m) * LOG2E) + ex2_fast((v0.y - m) * LOG2E)
       + ex2_fast((v0.z - m) * LOG2E) + ex2_fast((v0.w - m) * LOG2E);
    s += ex2_fast((v1.x - m) * LOG2E) + ex2_fast((v1.y - m) * LOG2E)
       + ex2_fast((v1.z - m) * LOG2E) + ex2_fast((v1.w - m) * LOG2E);
    s += ex2_fast((v2.x - m) * LOG2E) + ex2_fast((v2.y - m) * LOG2E)
       + ex2_fast((v2.z - m) * LOG2E) + ex2_fast((v2.w - m) * LOG2E);
    s += ex2_fast((v3.x - m) * LOG2E) + ex2_fast((v3.y - m) * LOG2E)
       + ex2_fast((v3.z - m) * LOG2E) + ex2_fast((v3.w - m) * LOG2E);
    #pragma unroll
    for (int o = 16; o > 0; o >>= 1) s += __shfl_xor_sync(0xffffffffu, s, o);

    if (lane == 0) {
        const float lse2 = m * LOG2E + lg2_fast(s);
        const int dgr = b * DR + t + u;
        g_blank_d[dgr * BS + u + 1] = v0.x * LOG2E - lse2;
        if (u < UU)
            g_emit_d[dgr * ES + u] = ev * LOG2E - lse2;
    }
}

// ---------------------------------------------------------------------------
// Kernel 2: branch-free warp-synchronous wavefront DP, one warp per batch.
// Paired-u (uA = 2*lane+1, uB = 2*lane+2). Software-pipelined shfl (issued at
// end of iter d for iter d+1); A/B lae2 chains hand-interleaved (B uses only
// pre-update vA/vB so the chains are independent). Loop runs only to
// dm = pl-1+tl; final alpha is simply the post-loop vA/vB.
// ---------------------------------------------------------------------------
__global__ void __launch_bounds__(256) rnnt_dp_kernel(
    const int* __restrict__ pred_len, const int* __restrict__ target_len,
    float* __restrict__ out)
{
    extern __shared__ float sm[];
    float* s_blank = sm;                 // DR*BS floats (21120)
    float* s_emit  = sm + DR * BS;       // DR*ES floats (20480)
    __shared__ float s_cum[DR];          // alpha[t][0] (log2)

    const int b   = blockIdx.x;
    const int tid = threadIdx.x;

    // Straight vector copies (diag-major, guards included as zeros)
    {
        const float4* sb4 = reinterpret_cast<const float4*>(g_blank_d + b * DR * BS);
        float4* db4 = reinterpret_cast<float4*>(s_blank);
        for (int i = tid; i < DR * BS / 4; i += 256) db4[i] = sb4[i];
        const float4* se4 = reinterpret_cast<const float4*>(g_emit_d + b * DR * ES);
        float4* de4 = reinterpret_cast<float4*>(s_emit);
        for (int i = tid; i < DR * ES / 4; i += 256) de4[i] = se4[i];
    }
    for (int i = tid; i < DR; i += 256) s_cum[i] = 0.f;
    __syncthreads();

    if (tid >= 32) return;
    const int lane = tid;
    const int pl = pred_len[b];
    const int tl = target_len[b];
    // blank(pl-1, tl) -> diag row pl-1+tl, col tl+1
    const float final_blank = s_blank[(pl - 1 + tl) * BS + tl + 1];

    // ---- u=0 column: exclusive prefix sum of blank[t][0] (warp scan) ----
    {
        float carry = 0.f;
        #pragma unroll
        for (int c = 0; c < 8; ++c) {
            const float bv = s_blank[(c * 32 + lane) * BS + 1];
            float inc = bv;
            #pragma unroll
            for (int o = 1; o < 32; o <<= 1) {
                const float n = __shfl_up_sync(0xffffffffu, inc, o);
                if (lane >= o) inc += n;
            }
            s_cum[c * 32 + lane] = carry + inc - bv;   // exclusive = alpha[t][0]
            carry += __shfl_sync(0xffffffffu, inc, 31);
        }
    }

    // ---- wavefront, paired u: uA = 2*lane+1, uB = 2*lane+2 ----
    const int uA = 2 * lane + 1;
    const int uB = 2 * lane + 2;
    float vA = NEGF, vB = NEGF;
    const int  src = (lane + 31) & 31;   // wrapped left-neighbor lane
    const bool l0  = (lane == 0);
    const int  dm  = pl - 1 + tl;        // last diagonal needed (>= 295)

    int ibl = 2 * lane + 2;              // s_blank, diag row d-1, col 2L+2
    int iem = 2 * lane;                  // s_emit,  diag row d-1, col 2L

    // software-pipelined neighbor: nB for iteration d computed at end of d-1
    float nB = __shfl_sync(0xffffffffu, vB, src);   // d=1: NEGF (correct)

    #pragma unroll 2
    for (int d = 1; d <= dm; ++d) {
        const float2 bl = *reinterpret_cast<const float2*>(s_blank + ibl);
        const float2 em = *reinterpret_cast<const float2*>(s_emit  + iem);
        const float cumv = s_cum[d - 1];
        ibl += BS; iem += ES;

        // inputs (B uses only pre-update values -> chains independent)
        const float yA = (l0 ? cumv : nB) + em.x;
        const float xA = vA + bl.x;
        const float yB = vA + em.y;          // left neighbor uB-1 = uA, old vA
        const float xB = vB + bl.y;

        // interleaved lae2 pair
        const float mmA = fmaxf(xA, yA);
        const float mmB = fmaxf(xB, yB);
        const float eA  = 0.f - fabsf(xA - yA);
        const float eB  = 0.f - fabsf(xB - yB);
        const float pA  = ex2_fast(eA);
        const float pB  = ex2_fast(eB);
        const float qA  = lg2_fast(1.f + pA);
        const float qB  = lg2_fast(1.f + pB);
        vA = mmA + qA;
        vB = mmB + qB;

        // shuffle for the NEXT iteration (latency hidden under loads/loop)
        nB = __shfl_sync(0xffffffffu, vB, src);
    }

    // after loop, vA/vB hold alpha on diagonal dm; capture at u == tl
    if (uA == tl) g_loss[b] = vA + final_blank;
    if (uB == tl) g_loss[b] = vB + final_blank;
    __syncwarp();

    // ---- finalize ticket (last DP block computes the mean) ----
    if (l0) {
        __threadfence();
        const int tkt = atomicAdd(&g_fin, 1);
        if (tkt == BB - 1) {
            __threadfence();
            float ssum = 0.f;
            #pragma unroll
            for (int q = 0; q < BB; ++q) ssum += g_loss[q];
            out[0] = -ssum * (LN2 / (float)BB);
            g_fin = 0;                                  // self-reset for replay
        }
    }
}

extern "C" void kernel_launch(void* const* d_in, const int* in_sizes, int n_in,
                              void* d_out, int out_size)
{
    const float* pred       = (const float*)d_in[0];
    const int*   target     = (const int*)  d_in[1];
    const int*   pred_len   = (const int*)  d_in[2];
    const int*   target_len = (const int*)  d_in[3];
    float*       out        = (float*)      d_out;

    (void)in_sizes; (void)n_in; (void)out_size;

    const int rows   = BB * TT * U1;               // 133120 rows
    const int wpb    = 256 / 32;
    const int blocks = (rows + wpb - 1) / wpb;     // 16640

    const int smem_bytes = (DR * BS + DR * ES) * (int)sizeof(float); // 166400
    cudaFuncSetAttribute(rnnt_dp_kernel,
                         cudaFuncAttributeMaxDynamicSharedMemorySize, smem_bytes);

    rnnt_softmax_kernel<<<blocks, 256>>>(pred, target);
    rnnt_dp_kernel<<<BB, 256, smem_bytes>>>(pred_len, target_len, out);
}

// round 16
// speedup vs baseline: 1.0840x; 1.0840x over previous
#include <cuda_runtime.h>
#include <math.h>

#define BB 8
#define TT 256
#define UU 64
#define VV 512
#define U1 (UU + 1)
#define DR 320                // diag rows per batch (t+u in 0..319)
#define BS 66                 // blank diag-row stride (col = u+1, even stride)
#define ES 64                 // emit diag-row stride (col = u)
#define NEGF (-1e30f)
#define LOG2E 1.4426950408889634f
#define LN2   0.6931471805599453f

// Diag-major scratch (log2 domain). blank(t,u) -> [b][t+u][u+1]; emit(t,u) ->
// [b][t+u][u]. Unwritten slots stay 0 from .bss (never stored to) and act as
// the guard zeros of the branch-free DP recurrence.
__device__ float g_blank_d[BB * DR * BS];
__device__ float g_emit_d [BB * DR * ES];
__device__ float g_loss   [BB];
__device__ int   g_fin;                   // finalize ticket; self-resets

__device__ __forceinline__ float ex2_fast(float x)
{
    float r; asm("ex2.approx.ftz.f32 %0, %1;" : "=f"(r) : "f"(x)); return r;
}
__device__ __forceinline__ float lg2_fast(float x)
{
    float r; asm("lg2.approx.f32 %0, %1;" : "=f"(r) : "f"(x)); return r;
}

// ---------------------------------------------------------------------------
// Kernel 1: per-row logsumexp over V=512 -> blank/emit log2-probs, written
// DIAG-MAJOR. One warp per (b,t,u) row; emit via direct gather.
// ---------------------------------------------------------------------------
__global__ void __launch_bounds__(256) rnnt_softmax_kernel(
    const float* __restrict__ pred, const int* __restrict__ target)
{
    const int warp = (blockIdx.x * blockDim.x + threadIdx.x) >> 5;
    const int lane = threadIdx.x & 31;
    const int rows = BB * TT * U1;
    if (warp >= rows) return;

    const int b   = warp / (TT * U1);
    const int rem = warp % (TT * U1);
    const int t   = rem / U1;
    const int u   = rem % U1;

    const float* rowp = pred + (size_t)warp * VV;
    const float4* row4 = reinterpret_cast<const float4*>(rowp);

    const int tgt = (u < UU) ? target[b * UU + u] : 0;
    const float ev = __ldg(rowp + tgt);

    float4 v0 = row4[lane];
    float4 v1 = row4[lane + 32];
    float4 v2 = row4[lane + 64];
    float4 v3 = row4[lane + 96];

    float m = fmaxf(fmaxf(fmaxf(v0.x, v0.y), fmaxf(v0.z, v0.w)),
                    fmaxf(fmaxf(v1.x, v1.y), fmaxf(v1.z, v1.w)));
    m = fmaxf(m, fmaxf(fmaxf(fmaxf(v2.x, v2.y), fmaxf(v2.z, v2.w)),
                       fmaxf(fmaxf(v3.x, v3.y), fmaxf(v3.z, v3.w))));
    #pragma unroll
    for (int o = 16; o > 0; o >>= 1) m = fmaxf(m, __shfl_xor_sync(0xffffffffu, m, o));

    float s = 0.f;
    s += ex2_fast((v0.x - m) * LOG2E) + ex2_fast((v0.y - m) * LOG2E)
       + ex2_fast((v0.z - m) * LOG2E) + ex2_fast((v0.w - m) * LOG2E);
    s += ex2_fast((v1.x - m) * LOG2E) + ex2_fast((v1.y - m) * LOG2E)
       + ex2_fast((v1.z - m) * LOG2E) + ex2_fast((v1.w - m) * LOG2E);
    s += ex2_fast((v2.x - m) * LOG2E) + ex2_fast((v2.y - m) * LOG2E)
       + ex2_fast((v2.z - m) * LOG2E) + ex2_fast((v2.w - m) * LOG2E);
    s += ex2_fast((v3.x - m) * LOG2E) + ex2_fast((v3.y - m) * LOG2E)
       + ex2_fast((v3.z - m) * LOG2E) + ex2_fast((v3.w - m) * LOG2E);
    #pragma unroll
    for (int o = 16; o > 0; o >>= 1) s += __shfl_xor_sync(0xffffffffu, s, o);

    if (lane == 0) {
        const float lse2 = m * LOG2E + lg2_fast(s);
        const int dgr = b * DR + t + u;
        g_blank_d[dgr * BS + u + 1] = v0.x * LOG2E - lse2;
        if (u < UU)
            g_emit_d[dgr * ES + u] = ev * LOG2E - lse2;
    }
}

// ---------------------------------------------------------------------------
// Kernel 2: branch-free warp-synchronous wavefront DP, one warp per batch.
// Paired-u (uA = 2*lane+1, uB = 2*lane+2). FIXED 319-trip loop (unroll 8) so
// ptxas front-batches the smem loads; A/B lae2 chains interleaved (B consumes
// only pre-update vA/vB -> independent); shfl software-pipelined (issued at
// end of iter d for d+1). 512 threads stage smem, warp 0 runs the wavefront.
// ---------------------------------------------------------------------------
__global__ void __launch_bounds__(512) rnnt_dp_kernel(
    const int* __restrict__ pred_len, const int* __restrict__ target_len,
    float* __restrict__ out)
{
    extern __shared__ float sm[];
    float* s_blank = sm;                 // DR*BS floats (21120)
    float* s_emit  = sm + DR * BS;       // DR*ES floats (20480)
    __shared__ float s_cum[DR];          // alpha[t][0] (log2)

    const int b   = blockIdx.x;
    const int tid = threadIdx.x;

    // Straight vector copies (diag-major, guards included as zeros)
    {
        const float4* sb4 = reinterpret_cast<const float4*>(g_blank_d + b * DR * BS);
        float4* db4 = reinterpret_cast<float4*>(s_blank);
        for (int i = tid; i < DR * BS / 4; i += 512) db4[i] = sb4[i];
        const float4* se4 = reinterpret_cast<const float4*>(g_emit_d + b * DR * ES);
        float4* de4 = reinterpret_cast<float4*>(s_emit);
        for (int i = tid; i < DR * ES / 4; i += 512) de4[i] = se4[i];
    }
    for (int i = tid; i < DR; i += 512) s_cum[i] = 0.f;
    __syncthreads();

    if (tid >= 32) return;
    const int lane = tid;
    const int pl = pred_len[b];
    const int tl = target_len[b];
    // blank(pl-1, tl) -> diag row pl-1+tl, col tl+1
    const float final_blank = s_blank[(pl - 1 + tl) * BS + tl + 1];

    // ---- u=0 column: exclusive prefix sum of blank[t][0] (warp scan) ----
    {
        float carry = 0.f;
        #pragma unroll
        for (int c = 0; c < 8; ++c) {
            const float bv = s_blank[(c * 32 + lane) * BS + 1];
            float inc = bv;
            #pragma unroll
            for (int o = 1; o < 32; o <<= 1) {
                const float n = __shfl_up_sync(0xffffffffu, inc, o);
                if (lane >= o) inc += n;
            }
            s_cum[c * 32 + lane] = carry + inc - bv;   // exclusive = alpha[t][0]
            carry += __shfl_sync(0xffffffffu, inc, 31);
        }
    }

    // ---- wavefront, paired u: uA = 2*lane+1, uB = 2*lane+2 ----
    const int uA = 2 * lane + 1;
    const int uB = 2 * lane + 2;
    float vA = NEGF, vB = NEGF;
    const int  src = (lane + 31) & 31;   // wrapped left-neighbor lane
    const bool l0  = (lane == 0);

    const int dm = pl - 1 + tl;          // capture diagonal (>= 295)
    const int dmatchA = (uA == tl) ? dm : -1;
    const int dmatchB = (uB == tl) ? dm : -1;
    float resA = 0.f, resB = 0.f;

    int ibl = 2 * lane + 2;              // s_blank, diag row d-1, col 2L+2
    int iem = 2 * lane;                  // s_emit,  diag row d-1, col 2L

    // software-pipelined neighbor: nB for iteration d computed at end of d-1
    float nB = __shfl_sync(0xffffffffu, vB, src);   // d=1: NEGF (correct)

    #pragma unroll 8
    for (int d = 1; d < TT + UU; ++d) {
        const float2 bl = *reinterpret_cast<const float2*>(s_blank + ibl);
        const float2 em = *reinterpret_cast<const float2*>(s_emit  + iem);
        const float cumv = s_cum[d - 1];
        ibl += BS; iem += ES;

        // inputs (B uses only pre-update values -> chains independent)
        const float yA = (l0 ? cumv : nB) + em.x;
        const float xA = vA + bl.x;
        const float yB = vA + em.y;          // left neighbor uB-1 = uA, old vA
        const float xB = vB + bl.y;

        // interleaved lae2 pair (pure MUFU)
        const float mmA = fmaxf(xA, yA);
        const float mmB = fmaxf(xB, yB);
        const float eA  = 0.f - fabsf(xA - yA);
        const float eB  = 0.f - fabsf(xB - yB);
        const float pA  = ex2_fast(eA);
        const float pB  = ex2_fast(eB);
        const float qA  = lg2_fast(1.f + pA);
        const float qB  = lg2_fast(1.f + pB);
        vA = mmA + qA;
        vB = mmB + qB;

        // shuffle for the NEXT iteration (latency hidden under loads/loop)
        nB = __shfl_sync(0xffffffffu, vB, src);

        resA = (d == dmatchA) ? vA : resA;
        resB = (d == dmatchB) ? vB : resB;
    }

    if (dmatchA >= 0) g_loss[b] = resA + final_blank;
    if (dmatchB >= 0) g_loss[b] = resB + final_blank;
    __syncwarp();

    // ---- finalize ticket (last DP block computes the mean) ----
    if (l0) {
        __threadfence();
        const int tkt = atomicAdd(&g_fin, 1);
        if (tkt == BB - 1) {
            __threadfence();
            float ssum = 0.f;
            #pragma unroll
            for (int q = 0; q < BB; ++q) ssum += g_loss[q];
            out[0] = -ssum * (LN2 / (float)BB);
            g_fin = 0;                                  // self-reset for replay
        }
    }
}

extern "C" void kernel_launch(void* const* d_in, const int* in_sizes, int n_in,
                              void* d_out, int out_size)
{
    const float* pred       = (const float*)d_in[0];
    const int*   target     = (const int*)  d_in[1];
    const int*   pred_len   = (const int*)  d_in[2];
    const int*   target_len = (const int*)  d_in[3];
    float*       out        = (float*)      d_out;

    (void)in_sizes; (void)n_in; (void)out_size;

    const int rows   = BB * TT * U1;               // 133120 rows
    const int wpb    = 256 / 32;
    const int blocks = (rows + wpb - 1) / wpb;     // 16640

    const int smem_bytes = (DR * BS + DR * ES) * (int)sizeof(float); // 166400
    cudaFuncSetAttribute(rnnt_dp_kernel,
                         cudaFuncAttributeMaxDynamicSharedMemorySize, smem_bytes);

    rnnt_softmax_kernel<<<blocks, 256>>>(pred, target);
    rnnt_dp_kernel<<<BB, 512, smem_bytes>>>(pred_len, target_len, out);
}

// round 17
// speedup vs baseline: 1.1191x; 1.0324x over previous
#include <cuda_runtime.h>
#include <math.h>

#define BB 8
#define TT 256
#define UU 64
#define VV 512
#define U1 (UU + 1)
#define DR 320                // diag rows per batch (t+u in 0..319)
#define BS 66                 // blank diag-row stride (col = u+1)
#define ES 64                 // emit diag-row stride (col = u)
#define WS 66                 // weight row stride (col = u-1; 8B-aligned rows)
#define NK 160                // pair-step rows (k = 0..159, row 0 unused)
#define NEGF (-1e30f)
#define LOG2E 1.4426950408889634f
#define LN2   0.6931471805599453f

// Diag-major scratch (log2 domain). blank(t,u) -> [b][t+u][u+1]; emit(t,u) ->
// [b][t+u][u]. Unwritten slots stay 0 from .bss and act as guard zeros.
__device__ float g_blank_d[BB * DR * BS];
__device__ float g_emit_d [BB * DR * ES];
__device__ float g_loss   [BB];
__device__ int   g_fin;                   // finalize ticket; self-resets

__device__ __forceinline__ float ex2_fast(float x)
{
    float r; asm("ex2.approx.ftz.f32 %0, %1;" : "=f"(r) : "f"(x)); return r;
}
__device__ __forceinline__ float lg2_fast(float x)
{
    float r; asm("lg2.approx.f32 %0, %1;" : "=f"(r) : "f"(x)); return r;
}
__device__ __forceinline__ float lae2(float x, float y)
{
    const float mm = fmaxf(x, y);
    return mm + lg2_fast(1.f + ex2_fast(0.f - fabsf(x - y)));
}

// ---------------------------------------------------------------------------
// Kernel 1: per-row logsumexp over V=512 -> blank/emit log2-probs, diag-major.
// ---------------------------------------------------------------------------
__global__ void __launch_bounds__(256) rnnt_softmax_kernel(
    const float* __restrict__ pred, const int* __restrict__ target)
{
    const int warp = (blockIdx.x * blockDim.x + threadIdx.x) >> 5;
    const int lane = threadIdx.x & 31;
    const int rows = BB * TT * U1;
    if (warp >= rows) return;

    const int b   = warp / (TT * U1);
    const int rem = warp % (TT * U1);
    const int t   = rem / U1;
    const int u   = rem % U1;

    const float* rowp = pred + (size_t)warp * VV;
    const float4* row4 = reinterpret_cast<const float4*>(rowp);

    const int tgt = (u < UU) ? target[b * UU + u] : 0;
    const float ev = __ldg(rowp + tgt);

    float4 v0 = row4[lane];
    float4 v1 = row4[lane + 32];
    float4 v2 = row4[lane + 64];
    float4 v3 = row4[lane + 96];

    float m = fmaxf(fmaxf(fmaxf(v0.x, v0.y), fmaxf(v0.z, v0.w)),
                    fmaxf(fmaxf(v1.x, v1.y), fmaxf(v1.z, v1.w)));
    m = fmaxf(m, fmaxf(fmaxf(fmaxf(v2.x, v2.y), fmaxf(v2.z, v2.w)),
                       fmaxf(fmaxf(v3.x, v3.y), fmaxf(v3.z, v3.w))));
    #pragma unroll
    for (int o = 16; o > 0; o >>= 1) m = fmaxf(m, __shfl_xor_sync(0xffffffffu, m, o));

    float s = 0.f;
    s += ex2_fast((v0.x - m) * LOG2E) + ex2_fast((v0.y - m) * LOG2E)
       + ex2_fast((v0.z - m) * LOG2E) + ex2_fast((v0.w - m) * LOG2E);
    s += ex2_fast((v1.x - m) * LOG2E) + ex2_fast((v1.y - m) * LOG2E)
       + ex2_fast((v1.z - m) * LOG2E) + ex2_fast((v1.w - m) * LOG2E);
    s += ex2_fast((v2.x - m) * LOG2E) + ex2_fast((v2.y - m) * LOG2E)
       + ex2_fast((v2.z - m) * LOG2E) + ex2_fast((v2.w - m) * LOG2E);
    s += ex2_fast((v3.x - m) * LOG2E) + ex2_fast((v3.y - m) * LOG2E)
       + ex2_fast((v3.z - m) * LOG2E) + ex2_fast((v3.w - m) * LOG2E);
    #pragma unroll
    for (int o = 16; o > 0; o >>= 1) s += __shfl_xor_sync(0xffffffffu, s, o);

    if (lane == 0) {
        const float lse2 = m * LOG2E + lg2_fast(s);
        const int dgr = b * DR + t + u;
        g_blank_d[dgr * BS + u + 1] = v0.x * LOG2E - lse2;
        if (u < UU)
            g_emit_d[dgr * ES + u] = ev * LOG2E - lse2;
    }
}

// ---------------------------------------------------------------------------
// Kernel 2: two-diagonal blocked wavefront DP. 512 threads precompute the
// combined pair-step weights (Wbb/Wm/Wee) in parallel; warp 0 then runs 159
// serial pair-steps (two diagonals per iteration) with a 3-way logsumexp.
// Paired-u: lane owns uA=2L+1 (cols 2L) and uB=2L+2 (cols 2L+1) -> aligned
// float2 LDS, conflict-free. Snapshot at diag dm&~1 + optional single step
// handles odd dm. Finalize via atomic ticket.
// ---------------------------------------------------------------------------
__global__ void __launch_bounds__(512) rnnt_dp_kernel(
    const int* __restrict__ pred_len, const int* __restrict__ target_len,
    float* __restrict__ out)
{
    extern __shared__ float sm[];
    float* s_wbb = sm;                    // NK*WS floats
    float* s_wm  = sm + NK * WS;
    float* s_wee = sm + 2 * NK * WS;
    __shared__ float s_cum[DR];           // alpha[t][0] (log2)

    const int b   = blockIdx.x;
    const int tid = threadIdx.x;
    const float* gb = g_blank_d + b * DR * BS;
    const float* ge = g_emit_d  + b * DR * ES;

    // ---- parallel weight precompute: cells (k=1..159, u=1..64) ----
    for (int idx = tid; idx < 159 * 64; idx += 512) {
        const int u = (idx & 63) + 1;
        const int k = (idx >> 6) + 1;
        const int rb2 = (2 * k - 2) * BS;   // blank diag row d-2
        const int rb1 = (2 * k - 1) * BS;   // blank diag row d-1
        const int re2 = (2 * k - 2) * ES;   // emit  diag row d-2
        const int re1 = (2 * k - 1) * ES;   // emit  diag row d-1

        const float B_t1_u  = gb[rb1 + u + 1];          // B(t-1,u)
        const float B_t2_u  = gb[rb2 + u + 1];          // B(t-2,u)
        const float B_t1_um = gb[rb2 + u];              // B(t-1,u-1)
        const float E_t1_um = ge[re2 + (u - 1)];        // E(t-1,u-1)
        const float E_t_um  = ge[re1 + (u - 1)];        // E(t,u-1)
        const float E_t_um2 = ge[re2 + max(u - 2, 0)];  // E(t,u-2) (u=1 junk, masked)

        s_wbb[k * WS + u - 1] = B_t2_u + B_t1_u;
        s_wm [k * WS + u - 1] = lae2(E_t1_um + B_t1_u, B_t1_um + E_t_um);
        s_wee[k * WS + u - 1] = E_t_um2 + E_t_um;
    }
    for (int i = tid; i < DR; i += 512) s_cum[i] = 0.f;
    __syncthreads();

    if (tid >= 32) return;
    const int lane = tid;
    const bool l0  = (lane == 0);
    const int  src = (lane + 31) & 31;
    const int pl = pred_len[b];
    const int tl = target_len[b];
    const int dm = pl - 1 + tl;           // final diagonal, in [295,319]
    const int ksnap = dm >> 1;            // snapshot pair-step (diag dm & ~1)

    // ---- u=0 column: exclusive prefix sum of blank(t,0) (global col 1) ----
    {
        float bv[8];
        #pragma unroll
        for (int c = 0; c < 8; ++c) bv[c] = gb[(c * 32 + lane) * BS + 1];
        float carry = 0.f;
        #pragma unroll
        for (int c = 0; c < 8; ++c) {
            float inc = bv[c];
            #pragma unroll
            for (int o = 1; o < 32; o <<= 1) {
                const float n = __shfl_up_sync(0xffffffffu, inc, o);
                if (lane >= o) inc += n;
            }
            s_cum[c * 32 + lane] = carry + inc - bv[c];   // exclusive = alpha[t][0]
            carry += __shfl_sync(0xffffffffu, inc, 31);
        }
    }
    __syncwarp();

    // ---- pair-step wavefront: uA = 2L+1, uB = 2L+2, two diagonals/iter ----
    float vA = NEGF, vB = NEGF;           // values on diag 2(k-1)
    float nA = NEGF, nB = NEGF;           // prev-lane vA,vB (pipelined shfl)
    float snapA = 0.f, snapB = 0.f;
    int iw = WS + 2 * lane;               // row k=1, col 2L

    #pragma unroll 4
    for (int k = 1; k <= 159; ++k) {
        const float2 wbb = *reinterpret_cast<const float2*>(s_wbb + iw);
        const float2 wm  = *reinterpret_cast<const float2*>(s_wm  + iw);
        const float2 wee = *reinterpret_cast<const float2*>(s_wee + iw);
        const float cumv = s_cum[2 * k - 2];
        iw += WS;

        // A: u = 2L+1  (neighbors on diag 2k-2: u-1 = prev vB, u-2 = prev vA)
        const float T1A = vA + wbb.x;
        const float T2A = (l0 ? cumv : nB) + wm.x;
        const float T3A = (l0 ? NEGF : nA) + wee.x;
        // B: u = 2L+2  (u-1 = own old vA, u-2 = prev vB; lane0: u-2=0 -> cum)
        const float T1B = vB + wbb.y;
        const float T2B = vA + wm.y;
        const float T3B = (l0 ? cumv : nB) + wee.y;

        const float mA = fmaxf(fmaxf(T1A, T2A), T3A);
        const float mB = fmaxf(fmaxf(T1B, T2B), T3B);
        const float sA = ex2_fast(T1A - mA) + ex2_fast(T2A - mA) + ex2_fast(T3A - mA);
        const float sB = ex2_fast(T1B - mB) + ex2_fast(T2B - mB) + ex2_fast(T3B - mB);
        vA = mA + lg2_fast(sA);
        vB = mB + lg2_fast(sB);

        nA = __shfl_sync(0xffffffffu, vA, src);
        nB = __shfl_sync(0xffffffffu, vB, src);

        snapA = (k == ksnap) ? vA : snapA;
        snapB = (k == ksnap) ? vB : snapB;
    }

    // ---- gather alpha at diag dm&~1 for u = tl and u = tl-1 ----
    const int lh = (tl - 1) >> 1;
    const float ah = __shfl_sync(0xffffffffu, snapA, lh);
    const float bh = __shfl_sync(0xffffffffu, snapB, lh);
    const float vH = (tl & 1) ? ah : bh;           // alpha(diag, tl)
    const int lg = (tl - 2) >> 1;
    const float ag = __shfl_sync(0xffffffffu, snapA, lg);
    const float bg = __shfl_sync(0xffffffffu, snapB, lg);
    const float vG = ((tl - 1) & 1) ? ag : bg;     // alpha(diag, tl-1)

    if (l0) {
        const float fb = gb[dm * BS + tl + 1];     // blank(pl-1,tl)
        float alpha;
        if (dm & 1) {
            // one single step dm-1 -> dm for cell (pl-1, tl)
            const float B1 = gb[(dm - 1) * BS + tl + 1];   // blank(pl-2,tl)
            const float E1 = ge[(dm - 1) * ES + tl - 1];   // emit(pl-1,tl-1)
            alpha = lae2(vH + B1, vG + E1);
        } else {
            alpha = vH;
        }
        g_loss[b] = alpha + fb;

        __threadfence();
        const int tkt = atomicAdd(&g_fin, 1);
        if (tkt == BB - 1) {
            __threadfence();
            float ssum = 0.f;
            #pragma unroll
            for (int q = 0; q < BB; ++q) ssum += g_loss[q];
            out[0] = -ssum * (LN2 / (float)BB);
            g_fin = 0;                              // self-reset for replay
        }
    }
}

extern "C" void kernel_launch(void* const* d_in, const int* in_sizes, int n_in,
                              void* d_out, int out_size)
{
    const float* pred       = (const float*)d_in[0];
    const int*   target     = (const int*)  d_in[1];
    const int*   pred_len   = (const int*)  d_in[2];
    const int*   target_len = (const int*)  d_in[3];
    float*       out        = (float*)      d_out;

    (void)in_sizes; (void)n_in; (void)out_size;

    const int rows   = BB * TT * U1;               // 133120 rows
    const int wpb    = 256 / 32;
    const int blocks = (rows + wpb - 1) / wpb;     // 16640

    const int smem_bytes = 3 * NK * WS * (int)sizeof(float);   // 126720
    cudaFuncSetAttribute(rnnt_dp_kernel,
                         cudaFuncAttributeMaxDynamicSharedMemorySize, smem_bytes);

    rnnt_softmax_kernel<<<blocks, 256>>>(pred, target);
    rnnt_dp_kernel<<<BB, 512, smem_bytes>>>(pred_len, target_len, out);
}